// round 4
// baseline (speedup 1.0000x reference)
#include <cuda_runtime.h>
#include <cstdint>

#define NB 256
#define NS 2048
#define NK 64
#define LN2F 0.69314718055994531f

// Scratch (device globals — no allocation allowed)
__device__ float g_vecA[NB][NK];
__device__ float g_vecB[NB][NK];
__device__ float g_offA[NB];
__device__ float g_offB[NB];
__device__ float g_gold[NB];
__device__ float g_loss[NB];

typedef unsigned long long u64;

__device__ __forceinline__ u64 fma2(u64 a, u64 b, u64 c) {
    u64 d; asm("fma.rn.f32x2 %0, %1, %2, %3;" : "=l"(d) : "l"(a), "l"(b), "l"(c)); return d;
}
__device__ __forceinline__ u64 add2(u64 a, u64 b) {
    u64 d; asm("add.rn.f32x2 %0, %1, %2;" : "=l"(d) : "l"(a), "l"(b)); return d;
}
__device__ __forceinline__ u64 pack2(float x, float y) {
    u64 d; asm("mov.b64 %0, {%1, %2};" : "=l"(d) : "f"(x), "f"(y)); return d;
}
__device__ __forceinline__ float2 unpack2(u64 v) {
    float2 f; asm("mov.b64 {%0, %1}, %2;" : "=f"(f.x), "=f"(f.y) : "l"(v)); return f;
}

// Half matvec: 32 i-values (dups in shared), 32 fma.f32x2, 16 LDS.128 broadcast.
__device__ __forceinline__ u64 matvec_half(const u64* __restrict__ base, const u64 (&Er)[32]) {
    const ulonglong2* qq = (const ulonglong2*)base;
    u64 c0 = 0, c1 = 0, c2 = 0, c3 = 0;
    #pragma unroll
    for (int g = 0; g < 8; g++) {
        ulonglong2 v0 = qq[2 * g];
        ulonglong2 v1 = qq[2 * g + 1];
        c0 = fma2(v0.x, Er[4 * g + 0], c0);
        c1 = fma2(v0.y, Er[4 * g + 1], c1);
        c2 = fma2(v1.x, Er[4 * g + 2], c2);
        c3 = fma2(v1.y, Er[4 * g + 3], c3);
    }
    return add2(add2(c0, c1), add2(c2, c3));
}

// One chain step. P = compile-time buffer parity. BUF = prefetch register.
// matvec half -> exchange partials -> 16 lanes/warp combine (add halves,
// * exp(score), * power-of-two scale), lane q==0 publishes next scale.
#define STEP(P, BUF) do {                                                    \
    u64 part_ = matvec_half(&adup[P][32 * w], Er);                           \
    zps[32 * w + l] = part_;                                                 \
    __syncthreads();                                                         \
    if (l < 16) {                                                            \
        float2 z_ = unpack2(add2(zps[q], zps[32 + q]));                      \
        float sc_ = sclbuf[P];                                               \
        float2 sv_ = BUF; BUF = *pre;                                        \
        float ax_ = z_.x * __expf(sv_.x) * sc_;                              \
        float ay_ = z_.y * __expf(sv_.y) * sc_;                              \
        off += (float)(127 - (__float_as_int(sc_) >> 23)) * LN2F;            \
        if (q == 0) {                                                        \
            int e_ = (__float_as_int(ax_) >> 23) & 0xff;                     \
            e_ = e_ < 1 ? 1 : (e_ > 253 ? 253 : e_);                         \
            sclbuf[P ^ 1] = __int_as_float((254 - e_) << 23);                \
        }                                                                    \
        ((ulonglong2*)&adup[P ^ 1][2 * q])[0] =                              \
            make_ulonglong2(pack2(ax_, ax_), pack2(ay_, ay_));               \
        fin.x = ax_; fin.y = ay_;                                            \
    }                                                                        \
    pre += dstep;                                                            \
    __syncthreads();                                                         \
} while (0)

// Final bwd half-step: matvec + add halves + apply pending scale (no exp).
#define STEP_NOEXP(P) do {                                                   \
    u64 part_ = matvec_half(&adup[P][32 * w], Er);                           \
    zps[32 * w + l] = part_;                                                 \
    __syncthreads();                                                         \
    if (l < 16) {                                                            \
        float2 z_ = unpack2(add2(zps[q], zps[32 + q]));                      \
        float sc_ = sclbuf[P];                                               \
        off += (float)(127 - (__float_as_int(sc_) >> 23)) * LN2F;            \
        fin.x = z_.x * sc_; fin.y = z_.y * sc_;                              \
    }                                                                        \
} while (0)

// Blocks [0,512): one half-chain per block, 2 warps i-split (1024 chain warps).
// Blocks [512,640): gold path, 1 warp per batch (256 batches).
__global__ void __launch_bounds__(64, 5)
crf_fused(const float* __restrict__ scores, const int* __restrict__ states,
          const float* __restrict__ trans, const float* __restrict__ source,
          const float* __restrict__ sink)
{
    const int w = threadIdx.x >> 5;   // warp in block: 0 or 1
    const int l = threadIdx.x & 31;

    if (blockIdx.x >= 512) {
        // ---------------- gold path ----------------
        const int b = (blockIdx.x - 512) * 2 + w;
        const int* st = states + b * NS;
        const float* sc = scores + (size_t)b * NS * NK;
        float acc = 0.f;
        #pragma unroll 4
        for (int t = l; t < NS; t += 32) {
            int s = st[t];
            float e = sc[t * NK + s];
            float tr = (t + 1 < NS) ? trans[s * NK + st[t + 1]] : 0.f;
            acc += e + tr;
        }
        #pragma unroll
        for (int d = 16; d; d >>= 1) acc += __shfl_xor_sync(0xffffffffu, acc, d);
        if (l == 0) g_gold[b] = acc + source[st[0]] + sink[st[NS - 1]];
        return;
    }

    // ---------------- one half-chain, 2-warp i-split ----------------
    __shared__ u64 adup[2][NK];    // dup-pair vector, double buffered
    __shared__ u64 zps[2 * 32];    // per-warp partials (pair per lane)
    __shared__ float sclbuf[2];    // power-of-two scale, double buffered

    const int g = blockIdx.x;      // half-chain id
    const int b = g >> 1;
    const bool fwd = (g & 1) == 0;
    const int q = 16 * w + (l & 15);   // output-pair index this lane combines

    // Er: this warp's half of exp(transition).
    u64 Er[32];
    if (fwd) {
        // fwd: lane l accumulates z[2l..2l+1]; Er[i2] = (E[i][2l], E[i][2l+1]), i = 32w+i2
        #pragma unroll
        for (int i2 = 0; i2 < 32; i2++) {
            int i = 32 * w + i2;
            float2 tv = ((const float2*)(trans + i * NK))[l];
            Er[i2] = pack2(expf(tv.x), expf(tv.y));
        }
    } else {
        // bwd: lane l accumulates beta[2l..2l+1]; Er[j2] = (E[2l][j], E[2l+1][j]), j = 32w+j2
        #pragma unroll
        for (int j2 = 0; j2 < 32; j2++) {
            int j = 32 * w + j2;
            Er[j2] = pack2(expf(trans[(2 * l) * NK + j]),
                           expf(trans[(2 * l + 1) * NK + j]));
        }
    }

    // Per-lane score pointer: row r -> pre0[r*32] (pair q within the row).
    const float2* pre0 = (const float2*)(scores + (size_t)b * NS * NK) + q;
    const int dstep = fwd ? 32 : -32;
    float off = 0.f;
    float2 fin = make_float2(0.f, 0.f);

    if (threadIdx.x == 0) { sclbuf[0] = 1.0f; sclbuf[1] = 1.0f; }

    // Init vector (combine lanes write dup-pairs).
    if (l < 16) {
        if (fwd) {
            // a_0 = exp(source + scores[b,0,:])
            float2 s0 = pre0[0];
            float2 sr = ((const float2*)source)[q];
            float ax = expf(sr.x + s0.x), ay = expf(sr.y + s0.y);
            ((ulonglong2*)&adup[0][2 * q])[0] =
                make_ulonglong2(pack2(ax, ax), pack2(ay, ay));
        } else {
            // w_2047 = exp(sink + scores[b,2047,:])
            float2 s0 = pre0[2047 * 32];
            float2 sk = ((const float2*)sink)[q];
            float wx = expf(sk.x + s0.x), wy = expf(sk.y + s0.y);
            ((ulonglong2*)&adup[0][2 * q])[0] =
                make_ulonglong2(pack2(wx, wx), pack2(wy, wy));
        }
    }
    __syncthreads();

    if (fwd) {
        const float2* pre = pre0 + 5 * 32;
        float2 b0 = pre0[1 * 32], b1 = pre0[2 * 32], b2 = pre0[3 * 32], b3 = pre0[4 * 32];
        // t = 1..1020 (255 groups of 4), then 1021..1023
        #pragma unroll 1
        for (int grp = 0; grp < 255; grp++) {
            STEP(0, b0); STEP(1, b1); STEP(0, b2); STEP(1, b3);
        }
        STEP(0, b0); STEP(1, b1); STEP(0, b2);

        if (l < 16) {
            g_vecA[b][2 * q] = fin.x;
            g_vecA[b][2 * q + 1] = fin.y;
            if (q == 0) g_offA[b] = off;
        }
    } else {
        const float2* pre = pre0 + 2042 * 32;
        float2 b0 = pre0[2046 * 32], b1 = pre0[2045 * 32], b2 = pre0[2044 * 32], b3 = pre0[2043 * 32];
        // m = 1..1020 (255 groups of 4), then 1021..1023, then final matvec
        #pragma unroll 1
        for (int grp = 0; grp < 255; grp++) {
            STEP(0, b0); STEP(1, b1); STEP(0, b2); STEP(1, b3);
        }
        STEP(0, b0); STEP(1, b1); STEP(0, b2);
        STEP_NOEXP(1);   // beta_1023 = E * w_1024 (scale applied, no emission)

        if (l < 16) {
            g_vecB[b][2 * q] = fin.x;
            g_vecB[b][2 * q + 1] = fin.y;
            if (q == 0) g_offB[b] = off;
        }
    }
}

// Per-batch loss: one block per batch.
__global__ void crf_loss()
{
    const int b = blockIdx.x;
    const int t = threadIdx.x;   // 64 threads
    const int w = t >> 5, l = t & 31;
    __shared__ float sh2[2];

    float p = g_vecA[b][t] * g_vecB[b][t];
    #pragma unroll
    for (int d = 16; d; d >>= 1) p += __shfl_xor_sync(0xffffffffu, p, d);
    if (l == 0) sh2[w] = p;
    __syncthreads();
    if (t == 0)
        g_loss[b] = logf(sh2[0] + sh2[1]) + g_offA[b] + g_offB[b] - g_gold[b];
}

// Mean over batches.
__global__ void crf_mean(float* __restrict__ out)
{
    const int b = threadIdx.x;   // 256
    __shared__ float red[256];
    red[b] = g_loss[b];
    __syncthreads();
    #pragma unroll
    for (int k = 128; k; k >>= 1) {
        if (b < k) red[b] += red[b + k];
        __syncthreads();
    }
    if (b == 0) out[0] = red[0] * (1.0f / NB);
}

// Alignment kernel so ncu (-s 5 -c 1) profiles crf_fused (launch idx 5 = pos 1 of replay 2).
__global__ void crf_nop() {}

extern "C" void kernel_launch(void* const* d_in, const int* in_sizes, int n_in,
                              void* d_out, int out_size)
{
    const float* scores = (const float*)d_in[0];
    const int*   states = (const int*)d_in[1];
    const float* trans  = (const float*)d_in[2];
    const float* source = (const float*)d_in[3];
    const float* sink   = (const float*)d_in[4];

    crf_nop<<<1, 32>>>();
    crf_fused<<<640, 64>>>(scores, states, trans, source, sink);
    crf_loss<<<NB, 64>>>();
    crf_mean<<<1, 256>>>((float*)d_out);
}

// round 5
// speedup vs baseline: 1.6519x; 1.6519x over previous
#include <cuda_runtime.h>
#include <cuda_bf16.h>
#include <cstdint>

#define NB 256
#define NS 2048
#define NK 64
#define LN2F 0.69314718055994531f

// Scratch (device globals — no allocation allowed)
__device__ float g_vecA[NB][NK];
__device__ float g_vecB[NB][NK];
__device__ float g_offA[NB];
__device__ float g_offB[NB];
__device__ float g_gold[NB];
__device__ float g_loss[NB];

typedef __nv_bfloat162 bf2;

__device__ __forceinline__ bf2 u2b(unsigned u) { return *reinterpret_cast<bf2*>(&u); }
__device__ __forceinline__ unsigned b2u(bf2 v) { return *reinterpret_cast<unsigned*>(&v); }

// matvec: z[2l..2l+1] = sum_i a[i] * E[i][2l..2l+1]
// 16x LDS.128 (broadcast, conflict-free) + 64x HFMA2 (rt 2), 4 acc chains.
__device__ __forceinline__ bf2 mv(const bf2* __restrict__ s, const unsigned (&Er)[NK]) {
    const uint4* q = (const uint4*)s;
    bf2 c0 = __floats2bfloat162_rn(0.f, 0.f);
    bf2 c1 = c0, c2 = c0, c3 = c0;
    #pragma unroll
    for (int g = 0; g < 16; g++) {
        uint4 v = q[g];
        c0 = __hfma2(u2b(v.x), u2b(Er[4 * g + 0]), c0);
        c1 = __hfma2(u2b(v.y), u2b(Er[4 * g + 1]), c1);
        c2 = __hfma2(u2b(v.z), u2b(Er[4 * g + 2]), c2);
        c3 = __hfma2(u2b(v.w), u2b(Er[4 * g + 3]), c3);
    }
    return __hadd2(__hadd2(c0, c1), __hadd2(c2, c3));
}

// Store (v.lo,v.lo),(v.hi,v.hi) dup-pairs as one STS.64 (2 PRMT + 1 STS).
__device__ __forceinline__ void store_dup(bf2* dst, bf2 v) {
    unsigned u = b2u(v);
    uint2 d;
    d.x = __byte_perm(u, u, 0x1010);
    d.y = __byte_perm(u, u, 0x3232);
    *reinterpret_cast<uint2*>(dst) = d;
}

// Exact power-of-two rescale (warp max via 5 shfl), offset in log domain.
__device__ __forceinline__ void rescale(bf2& v, float& off) {
    bf2 m2 = v;
    #pragma unroll
    for (int d = 16; d; d >>= 1)
        m2 = __hmax2(m2, u2b(__shfl_xor_sync(0xffffffffu, b2u(m2), d)));
    float m = fmaxf(__low2float(m2), __high2float(m2));
    int k = (__float_as_int(m) >> 23) - 127;
    k = k < -120 ? -120 : (k > 120 ? 120 : k);
    float scl = __int_as_float((127 - k) << 23);   // 2^-k (exact in bf16)
    v = __hmul2(v, __floats2bfloat162_rn(scl, scl));
    off += (float)k * LN2F;
}

// ---- forward step: matvec(read P) -> *exp(score) -> store P^1 ----
#define FSTEP(P, BUF) do {                                              \
    bf2 c_ = mv(myd[P], Er);                                            \
    float2 sv_ = BUF; BUF = *pre; pre += 32;                            \
    bf2 e_ = __floats2bfloat162_rn(__expf(sv_.x), __expf(sv_.y));       \
    av = __hmul2(c_, e_);                                               \
    store_dup(&myd[P ^ 1][2 * l], av);                                  \
    __syncwarp();                                                       \
} while (0)

#define FSTEP_R(P, BUF) do {                                            \
    bf2 c_ = mv(myd[P], Er);                                            \
    float2 sv_ = BUF; BUF = *pre; pre += 32;                            \
    bf2 e_ = __floats2bfloat162_rn(__expf(sv_.x), __expf(sv_.y));       \
    av = __hmul2(c_, e_);                                               \
    rescale(av, off);                                                   \
    store_dup(&myd[P ^ 1][2 * l], av);                                  \
    __syncwarp();                                                       \
} while (0)

// ---- backward step: w = av*exp(score) -> store P -> matvec(read P) ----
#define BSTEP(P, BUF) do {                                              \
    float2 sv_ = BUF; BUF = *pre; pre -= 32;                            \
    bf2 e_ = __floats2bfloat162_rn(__expf(sv_.x), __expf(sv_.y));       \
    bf2 w_ = __hmul2(av, e_);                                           \
    store_dup(&myd[P][2 * l], w_);                                      \
    __syncwarp();                                                       \
    av = mv(myd[P], Er);                                                \
} while (0)

#define BSTEP_R(P, BUF) do {                                            \
    float2 sv_ = BUF; BUF = *pre; pre -= 32;                            \
    bf2 e_ = __floats2bfloat162_rn(__expf(sv_.x), __expf(sv_.y));       \
    bf2 w_ = __hmul2(av, e_);                                           \
    rescale(w_, off);                                                   \
    store_dup(&myd[P][2 * l], w_);                                      \
    __syncwarp();                                                       \
    av = mv(myd[P], Er);                                                \
} while (0)

// Blocks [0,64): 8 warps x one half-chain each (512 half-chains, 2 warps/SMSP).
// Blocks [64,96): 8 warps x one gold-path batch each (256 batches).
__global__ void __launch_bounds__(256, 1)
crf_fused(const float* __restrict__ scores, const int* __restrict__ states,
          const float* __restrict__ trans, const float* __restrict__ source,
          const float* __restrict__ sink)
{
    const int w = threadIdx.x >> 5;
    const int l = threadIdx.x & 31;

    if (blockIdx.x >= 64) {
        // ---------------- gold path (one warp per batch) ----------------
        const int b = (blockIdx.x - 64) * 8 + w;
        const int* st = states + b * NS;
        const float* sc = scores + (size_t)b * NS * NK;
        float acc = 0.f;
        #pragma unroll 4
        for (int t = l; t < NS; t += 32) {
            int s = st[t];
            float e = sc[t * NK + s];
            float tr = (t + 1 < NS) ? trans[s * NK + st[t + 1]] : 0.f;
            acc += e + tr;
        }
        #pragma unroll
        for (int d = 16; d; d >>= 1) acc += __shfl_xor_sync(0xffffffffu, acc, d);
        if (l == 0) g_gold[b] = acc + source[st[0]] + sink[st[NS - 1]];
        return;
    }

    // ---------------- chains (one warp per half-chain, bf16) ----------------
    __shared__ bf2 adup[8][2][NK];   // [warp][double-buffer][dup bf16x2]  4KB
    const int g = blockIdx.x * 8 + w;
    const int b = g >> 1;
    const bool fwd = (g & 1) == 0;
    bf2 (*myd)[NK] = adup[w];

    // Er: exp(transition) in bf16x2 (column pair for fwd, row pair for bwd).
    unsigned Er[NK];
    if (fwd) {
        #pragma unroll
        for (int i = 0; i < NK; i++) {
            float2 tv = ((const float2*)(trans + i * NK))[l];
            Er[i] = b2u(__floats2bfloat162_rn(expf(tv.x), expf(tv.y)));
        }
    } else {
        #pragma unroll
        for (int j = 0; j < NK; j++) {
            Er[j] = b2u(__floats2bfloat162_rn(expf(trans[(2 * l) * NK + j]),
                                              expf(trans[(2 * l + 1) * NK + j])));
        }
    }

    const float2* pre0 = (const float2*)(scores + (size_t)b * NS * NK) + l;
    float off = 0.f;
    bf2 av;

    if (fwd) {
        // alpha_0 = exp(source + scores[b,0,:])
        float2 s0 = pre0[0];
        float2 sr = ((const float2*)source)[l];
        av = __floats2bfloat162_rn(expf(sr.x + s0.x), expf(sr.y + s0.y));
        store_dup(&myd[0][2 * l], av);
        __syncwarp();

        float2 f0 = pre0[1 * 32], f1 = pre0[2 * 32], f2 = pre0[3 * 32], f3 = pre0[4 * 32];
        const float2* pre = pre0 + 5 * 32;

        // t = 1..1016: 127 static groups of 8 (rescale on 8th)
        #pragma unroll 1
        for (int grp = 0; grp < 127; grp++) {
            FSTEP  (0, f0); FSTEP(1, f1); FSTEP(0, f2); FSTEP(1, f3);
            FSTEP  (0, f0); FSTEP(1, f1); FSTEP(0, f2); FSTEP_R(1, f3);
        }
        // tail t = 1017..1023 (7 steps; prefetch stays <= row 1027)
        FSTEP(0, f0); FSTEP(1, f1); FSTEP(0, f2); FSTEP(1, f3);
        FSTEP(0, f0); FSTEP(1, f1); FSTEP(0, f2);

        rescale(av, off);   // peg final vector so fp32 dot can't overflow
        g_vecA[b][2 * l] = __low2float(av);
        g_vecA[b][2 * l + 1] = __high2float(av);
        if (l == 0) g_offA[b] = off;
    } else {
        // beta seed = exp(sink); 1024 steps over rows 2047..1024
        float2 sk = ((const float2*)sink)[l];
        av = __floats2bfloat162_rn(expf(sk.x), expf(sk.y));

        float2 f0 = pre0[2047 * 32], f1 = pre0[2046 * 32], f2 = pre0[2045 * 32], f3 = pre0[2044 * 32];
        const float2* pre = pre0 + 2043 * 32;

        // 128 static groups of 8 (rescale on 8th; prefetch stays >= row 1020)
        #pragma unroll 1
        for (int grp = 0; grp < 128; grp++) {
            BSTEP  (0, f0); BSTEP(1, f1); BSTEP(0, f2); BSTEP(1, f3);
            BSTEP  (0, f0); BSTEP(1, f1); BSTEP(0, f2); BSTEP_R(1, f3);
        }

        rescale(av, off);   // peg final vector
        g_vecB[b][2 * l] = __low2float(av);
        g_vecB[b][2 * l + 1] = __high2float(av);
        if (l == 0) g_offB[b] = off;
    }
}

// Per-batch loss: one block per batch.
__global__ void crf_loss()
{
    const int b = blockIdx.x;
    const int t = threadIdx.x;   // 64 threads
    const int w = t >> 5, l = t & 31;
    __shared__ float sh2[2];

    float p = g_vecA[b][t] * g_vecB[b][t];
    #pragma unroll
    for (int d = 16; d; d >>= 1) p += __shfl_xor_sync(0xffffffffu, p, d);
    if (l == 0) sh2[w] = p;
    __syncthreads();
    if (t == 0)
        g_loss[b] = logf(sh2[0] + sh2[1]) + g_offA[b] + g_offB[b] - g_gold[b];
}

// Mean over batches.
__global__ void crf_mean(float* __restrict__ out)
{
    const int b = threadIdx.x;   // 256
    __shared__ float red[256];
    red[b] = g_loss[b];
    __syncthreads();
    #pragma unroll
    for (int k = 128; k; k >>= 1) {
        if (b < k) red[b] += red[b + k];
        __syncthreads();
    }
    if (b == 0) out[0] = red[0] * (1.0f / NB);
}

// Alignment kernel so ncu (-s 5 -c 1) lands on crf_fused.
__global__ void crf_nop() {}

extern "C" void kernel_launch(void* const* d_in, const int* in_sizes, int n_in,
                              void* d_out, int out_size)
{
    const float* scores = (const float*)d_in[0];
    const int*   states = (const int*)d_in[1];
    const float* trans  = (const float*)d_in[2];
    const float* source = (const float*)d_in[3];
    const float* sink   = (const float*)d_in[4];

    crf_nop<<<1, 32>>>();
    crf_fused<<<96, 256>>>(scores, states, trans, source, sink);
    crf_loss<<<NB, 64>>>();
    crf_mean<<<1, 256>>>((float*)d_out);
}

// round 6
// speedup vs baseline: 2.4856x; 1.5047x over previous
#include <cuda_runtime.h>
#include <cuda_bf16.h>
#include <cstdint>

#define NB 256
#define NS 2048
#define NK 64
#define LN2F 0.69314718055994531f
#define NBLK 96

// Scratch (device globals — no allocation allowed)
__device__ float g_vecA[NB][NK];
__device__ float g_vecB[NB][NK];
__device__ float g_offA[NB];
__device__ float g_offB[NB];
__device__ float g_gold[NB];
__device__ unsigned g_done;   // zero-init; reset by last block each launch

typedef __nv_bfloat162 bf2;

__device__ __forceinline__ bf2 u2b(unsigned u) { return *reinterpret_cast<bf2*>(&u); }
__device__ __forceinline__ unsigned b2u(bf2 v) { return *reinterpret_cast<unsigned*>(&v); }

// matvec: z[2l..2l+1] = sum_i a[i] * E[i][2l..2l+1]
// 16x LDS.128 (broadcast, conflict-free) + 64x HFMA2 (rt 2), 4 acc chains.
__device__ __forceinline__ bf2 mv(const bf2* __restrict__ s, const unsigned (&Er)[NK]) {
    const uint4* q = (const uint4*)s;
    bf2 c0 = __floats2bfloat162_rn(0.f, 0.f);
    bf2 c1 = c0, c2 = c0, c3 = c0;
    #pragma unroll
    for (int g = 0; g < 16; g++) {
        uint4 v = q[g];
        c0 = __hfma2(u2b(v.x), u2b(Er[4 * g + 0]), c0);
        c1 = __hfma2(u2b(v.y), u2b(Er[4 * g + 1]), c1);
        c2 = __hfma2(u2b(v.z), u2b(Er[4 * g + 2]), c2);
        c3 = __hfma2(u2b(v.w), u2b(Er[4 * g + 3]), c3);
    }
    return __hadd2(__hadd2(c0, c1), __hadd2(c2, c3));
}

// Store (v.lo,v.lo),(v.hi,v.hi) dup-pairs as one STS.64 (2 PRMT + 1 STS).
__device__ __forceinline__ void store_dup(bf2* dst, bf2 v) {
    unsigned u = b2u(v);
    uint2 d;
    d.x = __byte_perm(u, u, 0x1010);
    d.y = __byte_perm(u, u, 0x3232);
    *reinterpret_cast<uint2*>(dst) = d;
}

// Exact power-of-two rescale (warp max via 5 shfl), offset in log domain.
__device__ __forceinline__ void rescale(bf2& v, float& off) {
    bf2 m2 = v;
    #pragma unroll
    for (int d = 16; d; d >>= 1)
        m2 = __hmax2(m2, u2b(__shfl_xor_sync(0xffffffffu, b2u(m2), d)));
    float m = fmaxf(__low2float(m2), __high2float(m2));
    int k = (__float_as_int(m) >> 23) - 127;
    k = k < -120 ? -120 : (k > 120 ? 120 : k);
    float scl = __int_as_float((127 - k) << 23);   // 2^-k (exact in bf16)
    v = __hmul2(v, __floats2bfloat162_rn(scl, scl));
    off += (float)k * LN2F;
}

// ---- forward step: matvec(read P) -> *exp(score) -> store P^1 ----
#define FSTEP(P, BUF) do {                                              \
    bf2 c_ = mv(myd[P], Er);                                            \
    float2 sv_ = BUF; BUF = *pre; pre += 32;                            \
    bf2 e_ = __floats2bfloat162_rn(__expf(sv_.x), __expf(sv_.y));       \
    av = __hmul2(c_, e_);                                               \
    store_dup(&myd[P ^ 1][2 * l], av);                                  \
    __syncwarp();                                                       \
} while (0)

#define FSTEP_R(P, BUF) do {                                            \
    bf2 c_ = mv(myd[P], Er);                                            \
    float2 sv_ = BUF; BUF = *pre; pre += 32;                            \
    bf2 e_ = __floats2bfloat162_rn(__expf(sv_.x), __expf(sv_.y));       \
    av = __hmul2(c_, e_);                                               \
    rescale(av, off);                                                   \
    store_dup(&myd[P ^ 1][2 * l], av);                                  \
    __syncwarp();                                                       \
} while (0)

// ---- backward step: w = av*exp(score) -> store P -> matvec(read P) ----
#define BSTEP(P, BUF) do {                                              \
    float2 sv_ = BUF; BUF = *pre; pre -= 32;                            \
    bf2 e_ = __floats2bfloat162_rn(__expf(sv_.x), __expf(sv_.y));       \
    bf2 w_ = __hmul2(av, e_);                                           \
    store_dup(&myd[P][2 * l], w_);                                      \
    __syncwarp();                                                       \
    av = mv(myd[P], Er);                                                \
} while (0)

#define BSTEP_R(P, BUF) do {                                            \
    float2 sv_ = BUF; BUF = *pre; pre -= 32;                            \
    bf2 e_ = __floats2bfloat162_rn(__expf(sv_.x), __expf(sv_.y));       \
    bf2 w_ = __hmul2(av, e_);                                           \
    rescale(w_, off);                                                   \
    store_dup(&myd[P][2 * l], w_);                                      \
    __syncwarp();                                                       \
    av = mv(myd[P], Er);                                                \
} while (0)

// Blocks [0,64): 8 warps x one half-chain each (512 half-chains, 2 warps/SMSP).
// Blocks [64,96): 8 warps x one gold-path batch each (256 batches).
// Last block to finish computes the per-batch losses and the mean.
__global__ void __launch_bounds__(256, 1)
crf_fused(const float* __restrict__ scores, const int* __restrict__ states,
          const float* __restrict__ trans, const float* __restrict__ source,
          const float* __restrict__ sink, float* __restrict__ out)
{
    __shared__ bf2 adup[8][2][NK];   // chains: [warp][double-buffer][dup bf16x2]
    __shared__ float red[256];       // final block: loss reduction
    __shared__ int s_last;

    const int w = threadIdx.x >> 5;
    const int l = threadIdx.x & 31;

    if (blockIdx.x >= 64) {
        // ---------------- gold path (one warp per batch) ----------------
        const int b = (blockIdx.x - 64) * 8 + w;
        const int* st = states + b * NS;
        const float* sc = scores + (size_t)b * NS * NK;
        float acc = 0.f;
        #pragma unroll 4
        for (int t = l; t < NS; t += 32) {
            int s = st[t];
            float e = sc[t * NK + s];
            float tr = (t + 1 < NS) ? trans[s * NK + st[t + 1]] : 0.f;
            acc += e + tr;
        }
        #pragma unroll
        for (int d = 16; d; d >>= 1) acc += __shfl_xor_sync(0xffffffffu, acc, d);
        if (l == 0) g_gold[b] = acc + source[st[0]] + sink[st[NS - 1]];
    } else {
        // ---------------- chains (one warp per half-chain, bf16) ----------------
        const int g = blockIdx.x * 8 + w;
        const int b = g >> 1;
        const bool fwd = (g & 1) == 0;
        bf2 (*myd)[NK] = adup[w];

        // Er: exp(transition) in bf16x2 (column pair for fwd, row pair for bwd).
        unsigned Er[NK];
        if (fwd) {
            #pragma unroll
            for (int i = 0; i < NK; i++) {
                float2 tv = ((const float2*)(trans + i * NK))[l];
                Er[i] = b2u(__floats2bfloat162_rn(expf(tv.x), expf(tv.y)));
            }
        } else {
            #pragma unroll
            for (int j = 0; j < NK; j++) {
                Er[j] = b2u(__floats2bfloat162_rn(expf(trans[(2 * l) * NK + j]),
                                                  expf(trans[(2 * l + 1) * NK + j])));
            }
        }

        const float2* pre0 = (const float2*)(scores + (size_t)b * NS * NK) + l;
        float off = 0.f;
        bf2 av;

        if (fwd) {
            // alpha_0 = exp(source + scores[b,0,:])
            float2 s0 = pre0[0];
            float2 sr = ((const float2*)source)[l];
            av = __floats2bfloat162_rn(expf(sr.x + s0.x), expf(sr.y + s0.y));
            store_dup(&myd[0][2 * l], av);
            __syncwarp();

            // depth-8 prefetch ring: f0..f7 = rows 1..8, pre -> row 9
            float2 f0 = pre0[1 * 32], f1 = pre0[2 * 32], f2 = pre0[3 * 32], f3 = pre0[4 * 32];
            float2 f4 = pre0[5 * 32], f5 = pre0[6 * 32], f6 = pre0[7 * 32], f7 = pre0[8 * 32];
            const float2* pre = pre0 + 9 * 32;

            // t = 1..1016: 127 static groups of 8 (rescale on 8th)
            #pragma unroll 1
            for (int grp = 0; grp < 127; grp++) {
                FSTEP(0, f0); FSTEP(1, f1); FSTEP(0, f2); FSTEP(1, f3);
                FSTEP(0, f4); FSTEP(1, f5); FSTEP(0, f6); FSTEP_R(1, f7);
            }
            // tail t = 1017..1023 (7 steps; prefetch reads <= row 1031, in bounds)
            FSTEP(0, f0); FSTEP(1, f1); FSTEP(0, f2); FSTEP(1, f3);
            FSTEP(0, f4); FSTEP(1, f5); FSTEP(0, f6);

            rescale(av, off);   // peg final vector so fp32 dot can't overflow
            g_vecA[b][2 * l] = __low2float(av);
            g_vecA[b][2 * l + 1] = __high2float(av);
            if (l == 0) g_offA[b] = off;
        } else {
            // beta seed = exp(sink); 1024 steps over rows 2047..1024
            float2 sk = ((const float2*)sink)[l];
            av = __floats2bfloat162_rn(expf(sk.x), expf(sk.y));

            // depth-8 prefetch ring: f0..f7 = rows 2047..2040, pre -> row 2039
            float2 f0 = pre0[2047 * 32], f1 = pre0[2046 * 32], f2 = pre0[2045 * 32], f3 = pre0[2044 * 32];
            float2 f4 = pre0[2043 * 32], f5 = pre0[2042 * 32], f6 = pre0[2041 * 32], f7 = pre0[2040 * 32];
            const float2* pre = pre0 + 2039 * 32;

            // 128 static groups of 8 (rescale on 8th; prefetch reads >= row 1016)
            #pragma unroll 1
            for (int grp = 0; grp < 128; grp++) {
                BSTEP(0, f0); BSTEP(1, f1); BSTEP(0, f2); BSTEP(1, f3);
                BSTEP(0, f4); BSTEP(1, f5); BSTEP(0, f6); BSTEP_R(1, f7);
            }

            rescale(av, off);   // peg final vector
            g_vecB[b][2 * l] = __low2float(av);
            g_vecB[b][2 * l + 1] = __high2float(av);
            if (l == 0) g_offB[b] = off;
        }
    }

    // ---------------- completion: last block reduces ----------------
    __syncthreads();
    if (threadIdx.x == 0) {
        __threadfence();
        s_last = (atomicAdd(&g_done, 1u) == NBLK - 1u) ? 1 : 0;
    }
    __syncthreads();
    if (!s_last) return;
    __threadfence();

    const int b = threadIdx.x;   // one batch per thread
    float s = 0.f;
    #pragma unroll
    for (int j = 0; j < NK; j++) s += g_vecA[b][j] * g_vecB[b][j];
    float loss = logf(s) + g_offA[b] + g_offB[b] - g_gold[b];

    red[b] = loss;
    __syncthreads();
    #pragma unroll
    for (int k = 128; k; k >>= 1) {
        if (b < k) red[b] += red[b + k];
        __syncthreads();
    }
    if (b == 0) { out[0] = red[0] * (1.0f / NB); g_done = 0; }
}

extern "C" void kernel_launch(void* const* d_in, const int* in_sizes, int n_in,
                              void* d_out, int out_size)
{
    const float* scores = (const float*)d_in[0];
    const int*   states = (const int*)d_in[1];
    const float* trans  = (const float*)d_in[2];
    const float* source = (const float*)d_in[3];
    const float* sink   = (const float*)d_in[4];

    crf_fused<<<NBLK, 256>>>(scores, states, trans, source, sink, (float*)d_out);
}